// round 14
// baseline (speedup 1.0000x reference)
#include <cuda_runtime.h>
#include <math.h>
#include <cstdint>

#define NN 1024
#define ER 16384
#define ESTR 68               // es[k][edge] / ehe[edge][col] stride
#define HST  36               // proj transposed-h stride
#define NPROJ 96              // blocks that also run a projection unit
#define NBLK 256              // total blocks; each owns 64 edges
#define NREADY (NBLK + NPROJ) // claim arrivals + proj arrivals

// Scratch (allocation-free rule: __device__ globals).
// Self-cleaning: zero at module load; finalize returns all state to zero.
__device__ int   g_claim[NN * NN];   // 0 = empty; claim value = edge_idx+1
__device__ float g_Q[NN * 64];
__device__ float g_K[NN * 64];
__device__ float g_V[NN * 64];
__device__ float g_SVp[32 * 64];     // per-group partial V column sums (overwritten)
__device__ float g_acc[NN * 64];     // edge-delta value accumulator (self-reset)
__device__ float g_z[NN * 8];        // edge-delta normalizer (reset)
__device__ unsigned g_ready_cnt;     // claim + proj arrivals
__device__ unsigned g_ready_flag;    // set by last ready arriver (release)
__device__ unsigned g_done_cnt;      // edge-block completions
__device__ unsigned g_done_flag;     // set by last done arriver (release)
__device__ unsigned g_ack_cnt;       // finalize completions

__device__ __forceinline__ void cpa16(unsigned s, const void* g) {
    asm volatile("cp.async.cg.shared.global [%0], [%1], 16;" :: "r"(s), "l"(g));
}
#define CP_COMMIT() asm volatile("cp.async.commit_group;")
#define CP_WAIT(n)  asm volatile("cp.async.wait_group %0;" :: "n"(n))

__device__ __forceinline__ unsigned ld_acquire(unsigned* p) {
    unsigned v;
    asm volatile("ld.global.acquire.gpu.u32 %0, [%1];" : "=r"(v) : "l"(p) : "memory");
    return v;
}
__device__ __forceinline__ void st_release(unsigned* p, unsigned v) {
    asm volatile("st.global.release.gpu.u32 [%0], %1;" :: "l"(p), "r"(v) : "memory");
}

// 4x4-output-tile f32x2 GEMM over k=64 (A: [k][row] stride ESTR, B: [k][col] stride 64)
#define GEMM_64x64_BODY(ASRC, BSRC)                                                   \
    unsigned long long acc[4][2];                                                     \
    _Pragma("unroll")                                                                 \
    for (int i = 0; i < 4; i++) { acc[i][0] = 0ULL; acc[i][1] = 0ULL; }               \
    _Pragma("unroll 16")                                                              \
    for (int k = 0; k < 64; k++) {                                                    \
        float4 av = *reinterpret_cast<const float4*>(&ASRC[k * ESTR + ty * 4]);       \
        ulonglong2 bv = *reinterpret_cast<const ulonglong2*>(&BSRC[k * 64 + tx * 4]); \
        unsigned long long ad0, ad1, ad2, ad3;                                        \
        asm("mov.b64 %0, {%1,%1};" : "=l"(ad0) : "f"(av.x));                          \
        asm("mov.b64 %0, {%1,%1};" : "=l"(ad1) : "f"(av.y));                          \
        asm("mov.b64 %0, {%1,%1};" : "=l"(ad2) : "f"(av.z));                          \
        asm("mov.b64 %0, {%1,%1};" : "=l"(ad3) : "f"(av.w));                          \
        asm("fma.rn.f32x2 %0, %1, %2, %0;" : "+l"(acc[0][0]) : "l"(ad0), "l"(bv.x));  \
        asm("fma.rn.f32x2 %0, %1, %2, %0;" : "+l"(acc[0][1]) : "l"(ad0), "l"(bv.y));  \
        asm("fma.rn.f32x2 %0, %1, %2, %0;" : "+l"(acc[1][0]) : "l"(ad1), "l"(bv.x));  \
        asm("fma.rn.f32x2 %0, %1, %2, %0;" : "+l"(acc[1][1]) : "l"(ad1), "l"(bv.y));  \
        asm("fma.rn.f32x2 %0, %1, %2, %0;" : "+l"(acc[2][0]) : "l"(ad2), "l"(bv.x));  \
        asm("fma.rn.f32x2 %0, %1, %2, %0;" : "+l"(acc[2][1]) : "l"(ad2), "l"(bv.y));  \
        asm("fma.rn.f32x2 %0, %1, %2, %0;" : "+l"(acc[3][0]) : "l"(ad3), "l"(bv.x));  \
        asm("fma.rn.f32x2 %0, %1, %2, %0;" : "+l"(acc[3][1]) : "l"(ad3), "l"(bv.y));  \
    }

__global__ void __launch_bounds__(256, 2) fused_kernel(
    const float* __restrict__ h,
    const float* __restrict__ e,
    const float* __restrict__ WQ,
    const float* __restrict__ WK,
    const float* __restrict__ WV,
    const float* __restrict__ WE,
    const int* __restrict__ src,
    const int* __restrict__ dst,
    float* __restrict__ out) {
    __shared__ __align__(16) float sW[64 * 64];     // proj W          (16 KB)
    __shared__ __align__(16) float sHT[64 * HST];   // proj hT / SV scratch (9.2 KB)
    __shared__ __align__(16) float sA[64 * 64];     // WE              (16 KB)
    __shared__ __align__(16) float sB[64 * ESTR];   // es / ehe        (17.4 KB)
    __shared__ int s_sh[64], d_sh[64];
    __shared__ float svs[64];

    const int b = blockIdx.x;
    const int tid = threadIdx.x;
    const int tx = tid & 15, ty = tid >> 4;
    const int w = tid >> 5, lane = tid & 31;

    const float INVS = 0.35355339059327373f;  // 1/sqrt(8)
    const float SC   = 0.9090909090909091f;   // 1/(1+gamma)
    const float C0   = 0.09090909090909091f;  // gamma/(1+gamma)

    const bool is_proj = (b < NPROJ);
    const int m = b % 3;          // 0=Q,1=K,2=V (proj blocks only)
    const float* W = (m == 0) ? WQ : (m == 1) ? WK : WV;

    // ---- kick off async weight staging FIRST (background copies)
    if (is_proj) {
        unsigned swu = (unsigned)__cvta_generic_to_shared(sW);
#pragma unroll
        for (int q = 0; q < 4; q++)
            cpa16(swu + (tid + q * 256) * 16, (const char*)W + (tid + q * 256) * 16);
        CP_COMMIT();
    }
    {
        unsigned sau = (unsigned)__cvta_generic_to_shared(sA);
#pragma unroll
        for (int q = 0; q < 4; q++)
            cpa16(sau + (tid + q * 256) * 16, (const char*)WE + (tid + q * 256) * 16);
        CP_COMMIT();
    }

    // ---- every block: stage its 64 edge indices + claim them (dedup, last wins)
    int base = b * 64;
    if (tid < 64) {
        int s = src[base + tid], d = dst[base + tid];
        s_sh[tid] = s; d_sh[tid] = d;
        if (s != d) atomicMax(&g_claim[s * NN + d], base + tid + 1);
    }
    __threadfence();
    __syncthreads();
    if (tid == 0) {
        unsigned old = atomicAdd(&g_ready_cnt, 1u);
        if (old == NREADY - 1) st_release(&g_ready_flag, 1u);
    }

    // ---- e-tile transpose staging into sB (conflict-free: warp w owns
    //      k-slice w*8..w*8+7, lane = edge -> lane-consecutive STS addresses)
    {
#pragma unroll
        for (int hf = 0; hf < 2; hf++) {
            int edge = lane + hf * 32;
            const float4* ge = (const float4*)(e + (size_t)(base + edge) * 64 + w * 8);
#pragma unroll
            for (int q = 0; q < 2; q++) {
                float4 v = ge[q];
                int k0 = w * 8 + q * 4;
                sB[(k0 + 0) * ESTR + edge] = v.x;
                sB[(k0 + 1) * ESTR + edge] = v.y;
                sB[(k0 + 2) * ESTR + edge] = v.z;
                sB[(k0 + 3) * ESTR + edge] = v.w;
            }
        }
    }

    // ---- proj blocks: hT stage + proj GEMM (WE keeps streaming in background)
    if (is_proj) {
        int g = b / 3;
        int i0 = g * 32;
        {
            const float4* gh = (const float4*)(h + (size_t)(i0 + lane) * 64 + w * 8);
#pragma unroll
            for (int q = 0; q < 2; q++) {
                float4 v = gh[q];
                int k0 = w * 8 + q * 4;
                sHT[(k0 + 0) * HST + lane] = v.x;
                sHT[(k0 + 1) * HST + lane] = v.y;
                sHT[(k0 + 2) * HST + lane] = v.z;
                sHT[(k0 + 3) * HST + lane] = v.w;
            }
        }
        CP_WAIT(1);           // W landed (WE group may still be in flight)
        __syncthreads();

        unsigned long long pacc[2][2];
        pacc[0][0] = pacc[0][1] = pacc[1][0] = pacc[1][1] = 0ULL;
#pragma unroll 16
        for (int k = 0; k < 64; k++) {
            float2 av = *reinterpret_cast<const float2*>(&sHT[k * HST + ty * 2]);
            ulonglong2 bv = *reinterpret_cast<const ulonglong2*>(&sW[k * 64 + tx * 4]);
            unsigned long long ad0, ad1;
            asm("mov.b64 %0, {%1,%1};" : "=l"(ad0) : "f"(av.x));
            asm("mov.b64 %0, {%1,%1};" : "=l"(ad1) : "f"(av.y));
            asm("fma.rn.f32x2 %0, %1, %2, %0;" : "+l"(pacc[0][0]) : "l"(ad0), "l"(bv.x));
            asm("fma.rn.f32x2 %0, %1, %2, %0;" : "+l"(pacc[0][1]) : "l"(ad0), "l"(bv.y));
            asm("fma.rn.f32x2 %0, %1, %2, %0;" : "+l"(pacc[1][0]) : "l"(ad1), "l"(bv.x));
            asm("fma.rn.f32x2 %0, %1, %2, %0;" : "+l"(pacc[1][1]) : "l"(ad1), "l"(bv.y));
        }
        float* dstp = (m == 0) ? g_Q : (m == 1) ? g_K : g_V;
        float csum[4] = {0.f, 0.f, 0.f, 0.f};
#pragma unroll
        for (int i = 0; i < 2; i++) {
            float2 lo = *reinterpret_cast<float2*>(&pacc[i][0]);
            float2 hi = *reinterpret_cast<float2*>(&pacc[i][1]);
            float4 o = make_float4(lo.x, lo.y, hi.x, hi.y);
            *reinterpret_cast<float4*>(dstp + (size_t)(i0 + ty * 2 + i) * 64 + tx * 4) = o;
            csum[0] += o.x; csum[1] += o.y; csum[2] += o.z; csum[3] += o.w;
        }
        __syncthreads();   // all GEMM reads of sHT done
        if (m == 2) {
            *reinterpret_cast<float4*>(&sHT[ty * 64 + tx * 4]) =
                make_float4(csum[0], csum[1], csum[2], csum[3]);
            __syncthreads();
            if (tid < 64) {
                float sv = 0.f;
#pragma unroll
                for (int p = 0; p < 16; p++) sv += sHT[p * 64 + tid];
                g_SVp[g * 64 + tid] = sv;
            }
        }
        __threadfence();
        __syncthreads();
        if (tid == 0) {
            unsigned old = atomicAdd(&g_ready_cnt, 1u);
            if (old == NREADY - 1) st_release(&g_ready_flag, 1u);
        }
    }

    // ---- edge GEMM for ALL blocks (WE arrived via cp.async)
    CP_WAIT(0);
    __syncthreads();

    GEMM_64x64_BODY(sB, sA)
    __syncthreads();          // all GEMM reads of sB done before ehe overwrite

#pragma unroll
    for (int i = 0; i < 4; i++) {
        float2 lo = *reinterpret_cast<float2*>(&acc[i][0]);
        float2 hi = *reinterpret_cast<float2*>(&acc[i][1]);
        float4 o = make_float4(lo.x, lo.y, hi.x, hi.y);
        *reinterpret_cast<float4*>(&sB[(ty * 4 + i) * ESTR + tx * 4]) = o;
    }

    // wait for producers: cheap acquire-load polling (no atomic poll storm)
    if (tid == 0) {
        while (ld_acquire(&g_ready_flag) == 0u) { __nanosleep(64); }
    }
    __syncthreads();

    // ---------------- phase 2: warp w handles edges w*8..w*8+7, 2 per iter ----
    {
        int half = lane >> 4;     // 0 = edge A, 1 = edge B of the pair
        int q = lane & 15;        // column quad: cols q*4 .. q*4+3, head = q>>1
        int mk = w * 8 + (lane & 7);
        int cl = g_claim[s_sh[mk] * NN + d_sh[mk]];

        float4 Kv[4], Qv[4], Vv[4], EHv[4];
#pragma unroll
        for (int it = 0; it < 4; it++) {
            int kl = w * 8 + it * 2 + half;
            int s = s_sh[kl], d = d_sh[kl];
            Kv[it]  = *reinterpret_cast<const float4*>(&g_K[s * 64 + q * 4]);
            Qv[it]  = *reinterpret_cast<const float4*>(&g_Q[d * 64 + q * 4]);
            Vv[it]  = *reinterpret_cast<const float4*>(&g_V[s * 64 + q * 4]);
            EHv[it] = *reinterpret_cast<const float4*>(&sB[kl * ESTR + q * 4]);
        }
#pragma unroll
        for (int it = 0; it < 4; it++) {
            int kl = w * 8 + it * 2 + half;
            int cv = __shfl_sync(0xffffffffu, cl, it * 2 + half);
            bool valid = (cv == base + kl + 1);
            int d = d_sh[kl];
            float p = EHv[it].x * Kv[it].x * Qv[it].x;
            p = fmaf(EHv[it].y * Kv[it].y, Qv[it].y, p);
            p = fmaf(EHv[it].z * Kv[it].z, Qv[it].z, p);
            p = fmaf(EHv[it].w * Kv[it].w, Qv[it].w, p);
            p += __shfl_xor_sync(0xffffffffu, p, 1);   // 8-col head sum
            float d0 = __expf(fminf(fmaxf(p * INVS, -5.f), 5.f)) * SC - C0;
            if (valid) {
                float* ap = &g_acc[d * 64 + q * 4];
                asm volatile("red.global.add.v4.f32 [%0], {%1, %2, %3, %4};"
                             :: "l"(ap), "f"(d0 * Vv[it].x), "f"(d0 * Vv[it].y),
                                "f"(d0 * Vv[it].z), "f"(d0 * Vv[it].w) : "memory");
                if ((q & 1) == 0) atomicAdd(&g_z[d * 8 + (q >> 1)], d0);
            }
        }
    }

    // ======================= FINALIZE (every block: 4 rows) =======================
    __threadfence();
    __syncthreads();
    if (tid == 0) {
        unsigned old = atomicAdd(&g_done_cnt, 1u);
        if (old == NBLK - 1) st_release(&g_done_flag, 1u);
        while (ld_acquire(&g_done_flag) == 0u) { __nanosleep(64); }
    }
    __syncthreads();

    if (tid < 64) {
        float sv = 0.f;
#pragma unroll
        for (int p = 0; p < 32; p++) sv += g_SVp[p * 64 + tid];
        svs[tid] = sv;
    }
    __syncthreads();

    // rows 4b .. 4b+3  (256 floats = 64 float4)
    if (tid < 64) {
        int idx4 = b * 64 + tid;
        int idx = idx4 * 4;
        int j = idx >> 6;
        int c0 = idx & 63;
        int hh = c0 >> 3;
        float z = C0 * 1023.0f + g_z[j * 8 + hh] + 1e-6f;
        float rz = 1.0f / z;
        float4 a = ((const float4*)g_acc)[idx4];
        float4 v = ((const float4*)g_V)[idx4];
        float4 o;
        o.x = (C0 * (svs[c0 + 0] - v.x) + a.x) * rz;
        o.y = (C0 * (svs[c0 + 1] - v.y) + a.y) * rz;
        o.z = (C0 * (svs[c0 + 2] - v.z) + a.z) * rz;
        o.w = (C0 * (svs[c0 + 3] - v.w) + a.w) * rz;
        ((float4*)out)[idx4] = o;
        ((float4*)g_acc)[idx4] = make_float4(0.f, 0.f, 0.f, 0.f);  // self-reset
    }
    // claim reset for this block's own 64 edges (indices cached in smem)
    if (tid >= 64 && tid < 128) {
        int t = tid - 64;
        int s = s_sh[t], d = d_sh[t];
        if (s != d) g_claim[s * NN + d] = 0;  // benign same-value race on dups
    }
    __syncthreads();  // all g_z reads (tid<64) done before reset
    if (tid < 32) g_z[b * 32 + tid] = 0.f;

    __syncthreads();
    if (tid == 0) {
        unsigned a = atomicAdd(&g_ack_cnt, 1u);
        if (a == NBLK - 1) {  // last acker: everyone has exited the done-wait
            g_ready_cnt = 0u;
            g_ready_flag = 0u;
            g_done_cnt = 0u;
            g_done_flag = 0u;
            g_ack_cnt = 0u;
        }
    }
}

extern "C" void kernel_launch(void* const* d_in, const int* in_sizes, int n_in,
                              void* d_out, int out_size) {
    const float* h  = (const float*)d_in[0];
    const float* e  = (const float*)d_in[1];
    const float* WQ = (const float*)d_in[2];
    const float* WK = (const float*)d_in[3];
    const float* WE = (const float*)d_in[4];
    // d_in[5..7] = WQ2, WK2, WE2: unobservable (fake weights survive only
    // off-edge, where they equal the constant gamma/(1+gamma)).
    const float* WV = (const float*)d_in[8];
    const int* rs   = (const int*)d_in[9];
    const int* rd   = (const int*)d_in[10];
    float* out = (float*)d_out;

    fused_kernel<<<NBLK, 256>>>(h, e, WQ, WK, WV, WE, rs, rd, out);
}

// round 15
// speedup vs baseline: 1.0017x; 1.0017x over previous
#include <cuda_runtime.h>
#include <math.h>
#include <cstdint>

#define NN 1024
#define ER 16384
#define ESTR 68               // es[k][edge] / ehe[edge][col] stride
#define HST  36               // proj transposed-h stride
#define NPROJ 96              // proj work units (3 matrices x 32 node-groups)
#define NTILE 256             // edge tiles of 64 edges
#define NUNITS (NPROJ + NTILE)
#define NGRID 296             // 2 x 148 SMs, all co-resident
#define NREADY (NTILE + NPROJ) // 256 claim arrivals + 96 proj completions

// Scratch (allocation-free rule: __device__ globals).
// Self-cleaning: zero at module load; finalize returns all state to zero.
__device__ int   g_claim[NN * NN];   // 0 = empty; claim value = edge_idx+1
__device__ float g_Q[NN * 64];
__device__ float g_K[NN * 64];
__device__ float g_V[NN * 64];
__device__ float g_SVp[32 * 64];     // per-group partial V column sums (overwritten)
__device__ float g_acc[NN * 64];     // edge-delta value accumulator (self-reset)
__device__ float g_z[NN * 8];        // edge-delta normalizer (reset)
__device__ unsigned g_work;          // work-stealing queue head
__device__ unsigned g_ready_cnt;     // claim + proj arrivals
__device__ unsigned g_ready_flag;    // set by last ready arriver (release)
__device__ unsigned g_done_cnt;      // edge-tile completions
__device__ unsigned g_done_flag;     // set when all 256 tiles done (release)
__device__ unsigned g_ack_cnt;       // exit acks (all 296 blocks)

__device__ __forceinline__ void cpa16(unsigned s, const void* g) {
    asm volatile("cp.async.cg.shared.global [%0], [%1], 16;" :: "r"(s), "l"(g));
}
#define CP_COMMIT() asm volatile("cp.async.commit_group;")
#define CP_WAIT0()  asm volatile("cp.async.wait_group 0;")

__device__ __forceinline__ unsigned ld_acquire(unsigned* p) {
    unsigned v;
    asm volatile("ld.global.acquire.gpu.u32 %0, [%1];" : "=r"(v) : "l"(p) : "memory");
    return v;
}
__device__ __forceinline__ void st_release(unsigned* p, unsigned v) {
    asm volatile("st.global.release.gpu.u32 [%0], %1;" :: "l"(p), "r"(v) : "memory");
}

// 4x4-output-tile f32x2 GEMM over k=64 (A: [k][row] stride ESTR, B: [k][col] stride 64)
#define GEMM_64x64_BODY(ASRC, BSRC)                                                   \
    unsigned long long acc[4][2];                                                     \
    _Pragma("unroll")                                                                 \
    for (int i = 0; i < 4; i++) { acc[i][0] = 0ULL; acc[i][1] = 0ULL; }               \
    _Pragma("unroll 16")                                                              \
    for (int k = 0; k < 64; k++) {                                                    \
        float4 av = *reinterpret_cast<const float4*>(&ASRC[k * ESTR + ty * 4]);       \
        ulonglong2 bv = *reinterpret_cast<const ulonglong2*>(&BSRC[k * 64 + tx * 4]); \
        unsigned long long ad0, ad1, ad2, ad3;                                        \
        asm("mov.b64 %0, {%1,%1};" : "=l"(ad0) : "f"(av.x));                          \
        asm("mov.b64 %0, {%1,%1};" : "=l"(ad1) : "f"(av.y));                          \
        asm("mov.b64 %0, {%1,%1};" : "=l"(ad2) : "f"(av.z));                          \
        asm("mov.b64 %0, {%1,%1};" : "=l"(ad3) : "f"(av.w));                          \
        asm("fma.rn.f32x2 %0, %1, %2, %0;" : "+l"(acc[0][0]) : "l"(ad0), "l"(bv.x));  \
        asm("fma.rn.f32x2 %0, %1, %2, %0;" : "+l"(acc[0][1]) : "l"(ad0), "l"(bv.y));  \
        asm("fma.rn.f32x2 %0, %1, %2, %0;" : "+l"(acc[1][0]) : "l"(ad1), "l"(bv.x));  \
        asm("fma.rn.f32x2 %0, %1, %2, %0;" : "+l"(acc[1][1]) : "l"(ad1), "l"(bv.y));  \
        asm("fma.rn.f32x2 %0, %1, %2, %0;" : "+l"(acc[2][0]) : "l"(ad2), "l"(bv.x));  \
        asm("fma.rn.f32x2 %0, %1, %2, %0;" : "+l"(acc[2][1]) : "l"(ad2), "l"(bv.y));  \
        asm("fma.rn.f32x2 %0, %1, %2, %0;" : "+l"(acc[3][0]) : "l"(ad3), "l"(bv.x));  \
        asm("fma.rn.f32x2 %0, %1, %2, %0;" : "+l"(acc[3][1]) : "l"(ad3), "l"(bv.y));  \
    }

__global__ void __launch_bounds__(256, 2) fused_kernel(
    const float* __restrict__ h,
    const float* __restrict__ e,
    const float* __restrict__ WQ,
    const float* __restrict__ WK,
    const float* __restrict__ WV,
    const float* __restrict__ WE,
    const int* __restrict__ src,
    const int* __restrict__ dst,
    float* __restrict__ out) {
    __shared__ __align__(16) float sW[64 * 64];     // proj W          (16 KB)
    __shared__ __align__(16) float sHT[64 * HST];   // proj hT / SV scratch (9.2 KB)
    __shared__ __align__(16) float sA[64 * 64];     // WE              (16 KB)
    __shared__ __align__(16) float sB[64 * ESTR];   // es / ehe        (17.4 KB)
    __shared__ int s_sh[64], d_sh[64];
    __shared__ float svs[64];
    __shared__ unsigned s_u;

    const int b = blockIdx.x;
    const int tid = threadIdx.x;
    const int tx = tid & 15, ty = tid >> 4;
    const int w = tid >> 5, lane = tid & 31;

    const float INVS = 0.35355339059327373f;  // 1/sqrt(8)
    const float SC   = 0.9090909090909091f;   // 1/(1+gamma)
    const float C0   = 0.09090909090909091f;  // gamma/(1+gamma)

    // ---- stream WE into sA in the background (one group, drained at first use)
    {
        unsigned sau = (unsigned)__cvta_generic_to_shared(sA);
#pragma unroll
        for (int q = 0; q < 4; q++)
            cpa16(sau + (tid + q * 256) * 16, (const char*)WE + (tid + q * 256) * 16);
        CP_COMMIT();
    }

    // ---- blocks 0..255: claim slice b up-front (dedup, last duplicate wins).
    //      Pair kept in registers for the finalize claim-reset.
    int my_s = 0, my_d = 0;
    if (b < NTILE && tid < 64) {
        my_s = src[b * 64 + tid];
        my_d = dst[b * 64 + tid];
        if (my_s != my_d) atomicMax(&g_claim[my_s * NN + my_d], b * 64 + tid + 1);
    }
    if (b < NTILE) {
        __threadfence();
        __syncthreads();
        if (tid == 0) {
            unsigned old = atomicAdd(&g_ready_cnt, 1u);
            if (old == NREADY - 1) st_release(&g_ready_flag, 1u);
        }
    }

    bool ready_ok = false;   // meaningful on tid 0 only

    // ======================= WORK-STEALING LOOP =======================
    for (;;) {
        if (tid == 0) s_u = atomicAdd(&g_work, 1u);
        __syncthreads();
        unsigned u = s_u;
        if (u >= NUNITS) break;

        if (u < NPROJ) {
            // ---------------- proj unit u: m = u%3, 32-node group g = u/3 ----
            int m = u % 3;
            int g = u / 3;
            int i0 = g * 32;
            const float* W = (m == 0) ? WQ : (m == 1) ? WK : WV;
            {
                unsigned swu = (unsigned)__cvta_generic_to_shared(sW);
#pragma unroll
                for (int q = 0; q < 4; q++)
                    cpa16(swu + (tid + q * 256) * 16,
                          (const char*)W + (tid + q * 256) * 16);
                CP_COMMIT();
            }
            {
                // transposed stage: warp w covers k-range w*8..w*8+7, lane = node
                const float4* gh = (const float4*)(h + (size_t)(i0 + lane) * 64 + w * 8);
#pragma unroll
                for (int q = 0; q < 2; q++) {
                    float4 v = gh[q];
                    int k0 = w * 8 + q * 4;
                    sHT[(k0 + 0) * HST + lane] = v.x;
                    sHT[(k0 + 1) * HST + lane] = v.y;
                    sHT[(k0 + 2) * HST + lane] = v.z;
                    sHT[(k0 + 3) * HST + lane] = v.w;
                }
            }
            CP_WAIT0();
            __syncthreads();

            unsigned long long pacc[2][2];
            pacc[0][0] = pacc[0][1] = pacc[1][0] = pacc[1][1] = 0ULL;
#pragma unroll 16
            for (int k = 0; k < 64; k++) {
                float2 av = *reinterpret_cast<const float2*>(&sHT[k * HST + ty * 2]);
                ulonglong2 bv = *reinterpret_cast<const ulonglong2*>(&sW[k * 64 + tx * 4]);
                unsigned long long ad0, ad1;
                asm("mov.b64 %0, {%1,%1};" : "=l"(ad0) : "f"(av.x));
                asm("mov.b64 %0, {%1,%1};" : "=l"(ad1) : "f"(av.y));
                asm("fma.rn.f32x2 %0, %1, %2, %0;" : "+l"(pacc[0][0]) : "l"(ad0), "l"(bv.x));
                asm("fma.rn.f32x2 %0, %1, %2, %0;" : "+l"(pacc[0][1]) : "l"(ad0), "l"(bv.y));
                asm("fma.rn.f32x2 %0, %1, %2, %0;" : "+l"(pacc[1][0]) : "l"(ad1), "l"(bv.x));
                asm("fma.rn.f32x2 %0, %1, %2, %0;" : "+l"(pacc[1][1]) : "l"(ad1), "l"(bv.y));
            }
            float* dstp = (m == 0) ? g_Q : (m == 1) ? g_K : g_V;
            float csum[4] = {0.f, 0.f, 0.f, 0.f};
#pragma unroll
            for (int i = 0; i < 2; i++) {
                float2 lo = *reinterpret_cast<float2*>(&pacc[i][0]);
                float2 hi = *reinterpret_cast<float2*>(&pacc[i][1]);
                float4 o = make_float4(lo.x, lo.y, hi.x, hi.y);
                *reinterpret_cast<float4*>(dstp + (size_t)(i0 + ty * 2 + i) * 64 + tx * 4) = o;
                csum[0] += o.x; csum[1] += o.y; csum[2] += o.z; csum[3] += o.w;
            }
            __syncthreads();   // all GEMM reads of sHT/sW done
            if (m == 2) {
                *reinterpret_cast<float4*>(&sHT[ty * 64 + tx * 4]) =
                    make_float4(csum[0], csum[1], csum[2], csum[3]);
                __syncthreads();
                if (tid < 64) {
                    float sv = 0.f;
#pragma unroll
                    for (int p = 0; p < 16; p++) sv += sHT[p * 64 + tid];
                    g_SVp[g * 64 + tid] = sv;
                }
                __syncthreads();
            }
            __threadfence();
            if (tid == 0) {
                unsigned old = atomicAdd(&g_ready_cnt, 1u);
                if (old == NREADY - 1) st_release(&g_ready_flag, 1u);
            }
        } else {
            // ---------------- edge tile t = u - NPROJ (64 edges) ----
            int tbase = (int)(u - NPROJ) * 64;
            if (tid < 64) {
                s_sh[tid] = src[tbase + tid];
                d_sh[tid] = dst[tbase + tid];
            }
            // e-tile transpose stage (conflict-free: warp w owns k-slice, lane = edge)
            {
#pragma unroll
                for (int hf = 0; hf < 2; hf++) {
                    int edge = lane + hf * 32;
                    const float4* ge =
                        (const float4*)(e + (size_t)(tbase + edge) * 64 + w * 8);
#pragma unroll
                    for (int q = 0; q < 2; q++) {
                        float4 v = ge[q];
                        int k0 = w * 8 + q * 4;
                        sB[(k0 + 0) * ESTR + edge] = v.x;
                        sB[(k0 + 1) * ESTR + edge] = v.y;
                        sB[(k0 + 2) * ESTR + edge] = v.z;
                        sB[(k0 + 3) * ESTR + edge] = v.w;
                    }
                }
            }
            CP_WAIT0();        // WE resident (no-op after first tile)
            __syncthreads();

            GEMM_64x64_BODY(sB, sA)
            __syncthreads();   // all GEMM reads of sB done before ehe overwrite

#pragma unroll
            for (int i = 0; i < 4; i++) {
                float2 lo = *reinterpret_cast<float2*>(&acc[i][0]);
                float2 hi = *reinterpret_cast<float2*>(&acc[i][1]);
                float4 o = make_float4(lo.x, lo.y, hi.x, hi.y);
                *reinterpret_cast<float4*>(&sB[(ty * 4 + i) * ESTR + tx * 4]) = o;
            }

            // producers ready? (claims + all proj); cached after first pass
            if (tid == 0 && !ready_ok) {
                while (ld_acquire(&g_ready_flag) == 0u) { __nanosleep(64); }
                ready_ok = true;
            }
            __syncthreads();   // also publishes ehe writes block-wide

            // -------- phase 2: warp w handles edges w*8..w*8+7, 2 per iter ----
            {
                int half = lane >> 4;
                int q = lane & 15;       // cols q*4..q*4+3, head = q>>1
                int mk = w * 8 + (lane & 7);
                int cl = g_claim[s_sh[mk] * NN + d_sh[mk]];

                float4 Kv[4], Qv[4], Vv[4], EHv[4];
#pragma unroll
                for (int it = 0; it < 4; it++) {
                    int kl = w * 8 + it * 2 + half;
                    int s = s_sh[kl], d = d_sh[kl];
                    Kv[it]  = *reinterpret_cast<const float4*>(&g_K[s * 64 + q * 4]);
                    Qv[it]  = *reinterpret_cast<const float4*>(&g_Q[d * 64 + q * 4]);
                    Vv[it]  = *reinterpret_cast<const float4*>(&g_V[s * 64 + q * 4]);
                    EHv[it] = *reinterpret_cast<const float4*>(&sB[kl * ESTR + q * 4]);
                }
#pragma unroll
                for (int it = 0; it < 4; it++) {
                    int kl = w * 8 + it * 2 + half;
                    int cv = __shfl_sync(0xffffffffu, cl, it * 2 + half);
                    bool valid = (cv == tbase + kl + 1);
                    int d = d_sh[kl];
                    float p = EHv[it].x * Kv[it].x * Qv[it].x;
                    p = fmaf(EHv[it].y * Kv[it].y, Qv[it].y, p);
                    p = fmaf(EHv[it].z * Kv[it].z, Qv[it].z, p);
                    p = fmaf(EHv[it].w * Kv[it].w, Qv[it].w, p);
                    p += __shfl_xor_sync(0xffffffffu, p, 1);
                    float d0 = __expf(fminf(fmaxf(p * INVS, -5.f), 5.f)) * SC - C0;
                    if (valid) {
                        float* ap = &g_acc[d * 64 + q * 4];
                        asm volatile("red.global.add.v4.f32 [%0], {%1, %2, %3, %4};"
                                     :: "l"(ap), "f"(d0 * Vv[it].x), "f"(d0 * Vv[it].y),
                                        "f"(d0 * Vv[it].z), "f"(d0 * Vv[it].w) : "memory");
                        if ((q & 1) == 0) atomicAdd(&g_z[d * 8 + (q >> 1)], d0);
                    }
                }
            }
            __threadfence();
            __syncthreads();
            if (tid == 0) {
                unsigned old = atomicAdd(&g_done_cnt, 1u);
                if (old == NTILE - 1) st_release(&g_done_flag, 1u);
            }
        }
    }

    // ======================= DONE WAIT + FINALIZE =======================
    if (tid == 0) {
        while (ld_acquire(&g_done_flag) == 0u) { __nanosleep(64); }
    }
    __syncthreads();

    if (b < NTILE) {
        if (tid < 64) {
            float sv = 0.f;
#pragma unroll
            for (int p = 0; p < 32; p++) sv += g_SVp[p * 64 + tid];
            svs[tid] = sv;
        }
        __syncthreads();

        // rows 4b .. 4b+3 (64 float4) + claim reset from registers
        if (tid < 64) {
            int idx4 = b * 64 + tid;
            int idx = idx4 * 4;
            int j = idx >> 6;
            int c0 = idx & 63;
            int hh = c0 >> 3;
            float z = C0 * 1023.0f + g_z[j * 8 + hh] + 1e-6f;
            float rz = 1.0f / z;
            float4 a = ((const float4*)g_acc)[idx4];
            float4 v = ((const float4*)g_V)[idx4];
            float4 o;
            o.x = (C0 * (svs[c0 + 0] - v.x) + a.x) * rz;
            o.y = (C0 * (svs[c0 + 1] - v.y) + a.y) * rz;
            o.z = (C0 * (svs[c0 + 2] - v.z) + a.z) * rz;
            o.w = (C0 * (svs[c0 + 3] - v.w) + a.w) * rz;
            ((float4*)out)[idx4] = o;
            ((float4*)g_acc)[idx4] = make_float4(0.f, 0.f, 0.f, 0.f);  // self-reset
            if (my_s != my_d) g_claim[my_s * NN + my_d] = 0;  // benign dup race
        }
        __syncthreads();   // all g_z reads (own rows) done before reset
        if (tid < 32) g_z[b * 32 + tid] = 0.f;
    }

    __syncthreads();
    if (tid == 0) {
        unsigned a = atomicAdd(&g_ack_cnt, 1u);
        if (a == NGRID - 1) {  // last acker: all blocks exited the done-wait
            g_work = 0u;
            g_ready_cnt = 0u;
            g_ready_flag = 0u;
            g_done_cnt = 0u;
            g_done_flag = 0u;
            g_ack_cnt = 0u;
        }
    }
}

extern "C" void kernel_launch(void* const* d_in, const int* in_sizes, int n_in,
                              void* d_out, int out_size) {
    const float* h  = (const float*)d_in[0];
    const float* e  = (const float*)d_in[1];
    const float* WQ = (const float*)d_in[2];
    const float* WK = (const float*)d_in[3];
    const float* WE = (const float*)d_in[4];
    // d_in[5..7] = WQ2, WK2, WE2: unobservable (fake weights survive only
    // off-edge, where they equal the constant gamma/(1+gamma)).
    const float* WV = (const float*)d_in[8];
    const int* rs   = (const int*)d_in[9];
    const int* rd   = (const int*)d_in[10];
    float* out = (float*)d_out;

    fused_kernel<<<NGRID, 256>>>(h, e, WQ, WK, WV, WE, rs, rd, out);
}